// round 13
// baseline (speedup 1.0000x reference)
#include <cuda_runtime.h>
#include <cuda_fp16.h>
#include <math.h>

#define SEGS     512
#define MAXD     512
#define NTBL     7            // pos 0+1 share a map -> pre-summed into table 0
#define GUARD    16           // guard segments each side (clamp-free eval)
#define SEGT     (SEGS + 2 * GUARD)   // 544 segments per table
#define TBLC     (NTBL * SEGT)        // 3808 entries per region
#define WDIM     512
#define HDIM     512
#define BATCH    16
#define CHAN     3
#define NW       1025

#define MAGIC     12582912.0f         // 1.5 * 2^23
#define MAGICBITS 0x4B400000u         // bit pattern of 12582912.0f

// packed f32x2 constants (lo|hi identical)
#define HALF2K    0x3F0000003F000000ULL
#define MAGIC2    0x4B4000004B400000ULL
#define NMAGIC2   0xCB400000CB400000ULL
#define NEG1_2    0xBF800000BF800000ULL

// element stride between consecutive batches at fixed channel: 3 * 2^18
#define BSTRIDE   (CHAN << 18)

struct PosConsts {
    float Cx[NTBL];
    float Cy[NTBL];
    float D [NTBL];              // includes the -0.5 midpoint shift
};

// Midpoint-centered per-segment quadratics, 1/8 folded in:
//   val(v) = C + v*(B + v*A),  v = ys - k,  ys = xs - 0.5
// 8-byte entry: .x = half2(A, B)  (A low, B high), .y = float C
// (C absorbs E[v^2]=1/12 of A's fp16 rounding error).
__device__ uint2 g_E[CHAN * TBLC];

__global__ __launch_bounds__(256)
void prep_coef_kernel(const float* __restrict__ wts)
{
    int idx = blockIdx.x * 256 + threadIdx.x;           // [0, 3*7*544)
    if (idx >= CHAN * TBLC) return;
    int j   = idx % SEGT;                               // 0..543
    int ct  = idx / SEGT;
    int c   = ct / NTBL;
    int tbl = ct - c * NTBL;

    int k  = j - GUARD;                                 // segment id (may be out of range)
    int kk = k < 0 ? 0 : (k > SEGS - 1 ? SEGS - 1 : k); // clamped source segment
    double delta = (double)(k - kk);

    double A, B, C;
    {
        auto coef = [&](int pos, double& a, double& b, double& cc) {
            const float* w = wts + (pos * CHAN + c) * NW + 2 * kk;
            double w0 = w[0], w1 = w[1], w2 = w[2];
            a  = 2.0 * (w0 + w2) - 4.0 * w1;
            b  = w2 - w0;
            cc = w1;
        };
        if (tbl == 0) {                                  // pos 0 + pos 1 summed
            double a0, b0, c0, a1, b1, c1;
            coef(0, a0, b0, c0);
            coef(1, a1, b1, c1);
            A = a0 + a1; B = b0 + b1; C = c0 + c1;
        } else {
            coef(tbl + 1, A, B, C);
        }
    }
    // re-center by delta: q_guard(v) = q_src(v + delta)
    double Bg = B + 2.0 * A * delta;
    double Cg = C + B * delta + A * delta * delta;

    double As = 0.125 * A, Bs = 0.125 * Bg, Cs = 0.125 * Cg;

    // fp16 quantize A, B; fold E[v^2]=1/12 of A's rounding error into C
    __half Ah = __float2half_rn((float)As);
    __half Bh = __float2half_rn((float)Bs);
    Cs += (As - (double)__half2float(Ah)) / 12.0;

    __half2 ab = __halves2half2(Ah, Bh);                 // A low, B high
    uint2 e;
    e.x = *reinterpret_cast<unsigned*>(&ab);
    e.y = __float_as_uint((float)Cs);
    g_E[c * TBLC + tbl * SEGT + j] = e;
}

// ---- packed f32x2 helpers ----
__device__ __forceinline__ unsigned long long fma2(unsigned long long a,
                                                   unsigned long long b,
                                                   unsigned long long c)
{
    unsigned long long d;
    asm("fma.rn.f32x2 %0, %1, %2, %3;" : "=l"(d) : "l"(a), "l"(b), "l"(c));
    return d;
}
__device__ __forceinline__ unsigned long long add2(unsigned long long a,
                                                   unsigned long long b)
{
    unsigned long long d;
    asm("add.rn.f32x2 %0, %1, %2;" : "=l"(d) : "l"(a), "l"(b));
    return d;
}
__device__ __forceinline__ unsigned long long pack2(float lo, float hi)
{
    unsigned long long d;
    asm("mov.b64 %0, {%1, %2};" : "=l"(d) : "f"(lo), "f"(hi));
    return d;
}
__device__ __forceinline__ void unpack2u(unsigned long long v, unsigned& lo, unsigned& hi)
{
    asm("mov.b64 {%0, %1}, %2;" : "=r"(lo), "=r"(hi) : "l"(v));
}
// pack two f32 into one half2 register: low = lo, high = hi
__device__ __forceinline__ unsigned cvt_f16x2(float lo, float hi)
{
    unsigned d;
    asm("cvt.rn.f16x2.f32 %0, %1, %2;" : "=r"(d) : "f"(hi), "f"(lo));
    return d;
}

__global__ __launch_bounds__(256, 6)
void stripe_poly_kernel(const float* __restrict__ x,
                        float* __restrict__ out,
                        PosConsts pc)
{
    __shared__ uint2 sE[TBLC];                           // 30464 B

    const int c = blockIdx.y;

    for (int k = threadIdx.x; k < TBLC; k += 256)
        sE[k] = g_E[c * TBLC + k];
    __syncthreads();

    // thread owns ONE pixel (adjacent lanes = adjacent h -> conflict-free
    // gather footprint); processes FOUR batches per iter as two independent
    // packed pairs for ILP. A/B part in native half2, C in fp32.
    const int pixel = blockIdx.x * 256 + threadIdx.x;    // grid.x*256 == 512*512
    const float wx = (float)(pixel >> 9);
    const float hy = (float)(pixel & 511);

    float P[NTBL];
#pragma unroll
    for (int i = 0; i < NTBL; i++)
        P[i] = fmaf(pc.Cx[i], wx, fmaf(pc.Cy[i], hy, pc.D[i]));

    // single base pointer per quad; batch offsets are compile-time constants
    const float* __restrict__ xb = x   + (c << 18) + pixel;
    float*       __restrict__ ob = out + (c << 18) + pixel;

#pragma unroll 1
    for (int bq = 0; bq < BATCH / 4; bq++) {
        const int base = 4 * bq * BSTRIDE;
        unsigned long long xpA = pack2(xb[base],               xb[base + BSTRIDE]);
        unsigned long long xpB = pack2(xb[base + 2 * BSTRIDE], xb[base + 3 * BSTRIDE]);
        __half2 accUA = __float2half2_rn(0.f);
        __half2 accUB = __float2half2_rn(0.f);
        float accC0 = 0.f, accC1 = 0.f, accC2 = 0.f, accC3 = 0.f;
#pragma unroll
        for (int i = 0; i < NTBL; i++) {
            unsigned long long PP = pack2(P[i], P[i]);   // shared by both pairs
            const unsigned OFS = (unsigned)(i * SEGT + GUARD) - MAGICBITS;

            // ---- pair A ----
            unsigned long long ysA = fma2(HALF2K, xpA, PP);
            unsigned long long gA  = add2(ysA, MAGIC2);
            unsigned long long sfA = add2(gA, NMAGIC2);
            unsigned long long vA  = fma2(sfA, NEG1_2, ysA);
            // ---- pair B ----
            unsigned long long ysB = fma2(HALF2K, xpB, PP);
            unsigned long long gB  = add2(ysB, MAGIC2);
            unsigned long long sfB = add2(gB, NMAGIC2);
            unsigned long long vB  = fma2(sfB, NEG1_2, ysB);

            unsigned ga0, ga1, gb0, gb1;
            unpack2u(gA, ga0, ga1);
            unpack2u(gB, gb0, gb1);
            uint2 t0 = sE[ga0 + OFS];
            uint2 t1 = sE[ga1 + OFS];
            uint2 t2 = sE[gb0 + OFS];
            uint2 t3 = sE[gb1 + OFS];

            unsigned va0, va1, vb0, vb1;
            unpack2u(vA, va0, va1);
            unpack2u(vB, vb0, vb1);
            unsigned v2A = cvt_f16x2(__uint_as_float(va0), __uint_as_float(va1));
            unsigned v2B = cvt_f16x2(__uint_as_float(vb0), __uint_as_float(vb1));

            unsigned A2A = __byte_perm(t0.x, t1.x, 0x5410);
            unsigned B2A = __byte_perm(t0.x, t1.x, 0x7632);
            unsigned A2B = __byte_perm(t2.x, t3.x, 0x5410);
            unsigned B2B = __byte_perm(t2.x, t3.x, 0x7632);

            __half2 vhA = *reinterpret_cast<__half2*>(&v2A);
            __half2 vhB = *reinterpret_cast<__half2*>(&v2B);
            __half2 AA  = *reinterpret_cast<__half2*>(&A2A);
            __half2 BA  = *reinterpret_cast<__half2*>(&B2A);
            __half2 AB  = *reinterpret_cast<__half2*>(&A2B);
            __half2 BB  = *reinterpret_cast<__half2*>(&B2B);

            accUA = __hfma2(vhA, __hfma2(vhA, AA, BA), accUA);
            accUB = __hfma2(vhB, __hfma2(vhB, AB, BB), accUB);

            accC0 += __uint_as_float(t0.y);
            accC1 += __uint_as_float(t1.y);
            accC2 += __uint_as_float(t2.y);
            accC3 += __uint_as_float(t3.y);
        }
        ob[base]               = __low2float(accUA)  + accC0;
        ob[base + BSTRIDE]     = __high2float(accUA) + accC1;
        ob[base + 2 * BSTRIDE] = __low2float(accUB)  + accC2;
        ob[base + 3 * BSTRIDE] = __high2float(accUB) + accC3;
    }
}

extern "C" void kernel_launch(void* const* d_in, const int* in_sizes, int n_in,
                              void* d_out, int out_size)
{
    const float* x   = (const float*)d_in[0];   // [16, 3, 512, 512]
    const float* wts = (const float*)d_in[1];   // [8, 3, 1025]
    float* out = (float*)d_out;

    // Fold position maps analytically (host, double precision):
    //   xs = 0.5*x + (r - rmin)*S,  S = RATIO*512/dr,  r = cx*w + sgn*cy*h
    //   D additionally absorbs the -0.5 midpoint shift (ys = xs - 0.5).
    PosConsts pc;
    const double RATIO = (double)MAXD / (double)(MAXD + 1);
    for (int rot = 0; rot < 4; rot++) {
        double theta = (M_PI / 2.0) * ((double)rot / 4.0);
        double cx = cos(theta), cy = sin(theta);
        for (int s = 0; s < 2; s++) {
            int pos = rot * 2 + s;
            int tbl = (pos <= 1) ? 0 : pos - 1;          // pos 0,1 -> table 0
            double sgn  = (s == 0) ? 1.0 : -1.0;
            double rmin = (s == 0) ? 0.0 : -cy * (HDIM - 1);
            double rmax = (s == 0) ? (cx + cy) * (WDIM - 1) : cx * (WDIM - 1);
            double dr   = rmax - rmin;
            double S    = RATIO * (double)MAXD / dr;
            pc.Cx[tbl] = (float)(cx * S);
            pc.Cy[tbl] = (float)(sgn * cy * S);
            pc.D [tbl] = (float)(-rmin * S - 0.5);
        }
    }

    prep_coef_kernel<<<(CHAN * TBLC + 255) / 256, 256>>>(wts);

    dim3 grid(WDIM * HDIM / 256, CHAN, 1);               // (1024, 3)
    stripe_poly_kernel<<<grid, 256>>>(x, out, pc);
}

// round 14
// speedup vs baseline: 1.0825x; 1.0825x over previous
#include <cuda_runtime.h>
#include <cuda_fp16.h>
#include <math.h>

#define SEGS     512
#define MAXD     512
#define NTBL     7            // pos 0+1 share a map -> pre-summed into table 0
#define GUARD    16           // guard segments each side (clamp-free eval)
#define SEGT     (SEGS + 2 * GUARD)   // 544 segments per table
#define TBLC     (NTBL * SEGT)        // 3808 entries per region
#define WDIM     512
#define HDIM     512
#define BATCH    16
#define CHAN     3
#define NW       1025

#define MAGIC     12582912.0f         // 1.5 * 2^23
#define MAGICBITS 0x4B400000u         // bit pattern of 12582912.0f

// packed f32x2 constants (lo|hi identical)
#define HALF2K    0x3F0000003F000000ULL
#define MAGIC2    0x4B4000004B400000ULL
#define NMAGIC2   0xCB400000CB400000ULL
#define NEG1_2    0xBF800000BF800000ULL

struct PosConsts {
    float Cx[NTBL];
    float Cy[NTBL];
    float D [NTBL];    // includes -0.5 midpoint shift AND the table base i*SEGT+GUARD
};

// Midpoint-centered per-segment quadratics, 1/8 folded in:
//   val(v) = C + v*(B + v*A),  v = ys - round(ys)
// 8-byte entry: .x = half2(A, B)  (A low, B high), .y = float C
// (C absorbs E[v^2]=1/12 of A's fp16 rounding error).
__device__ uint2 g_E[CHAN * TBLC];

__global__ __launch_bounds__(256)
void prep_coef_kernel(const float* __restrict__ wts)
{
    int idx = blockIdx.x * 256 + threadIdx.x;           // [0, 3*7*544)
    if (idx >= CHAN * TBLC) return;
    int j   = idx % SEGT;                               // 0..543
    int ct  = idx / SEGT;
    int c   = ct / NTBL;
    int tbl = ct - c * NTBL;

    int k  = j - GUARD;                                 // segment id (may be out of range)
    int kk = k < 0 ? 0 : (k > SEGS - 1 ? SEGS - 1 : k); // clamped source segment
    double delta = (double)(k - kk);

    double A, B, C;
    {
        auto coef = [&](int pos, double& a, double& b, double& cc) {
            const float* w = wts + (pos * CHAN + c) * NW + 2 * kk;
            double w0 = w[0], w1 = w[1], w2 = w[2];
            a  = 2.0 * (w0 + w2) - 4.0 * w1;
            b  = w2 - w0;
            cc = w1;
        };
        if (tbl == 0) {                                  // pos 0 + pos 1 summed
            double a0, b0, c0, a1, b1, c1;
            coef(0, a0, b0, c0);
            coef(1, a1, b1, c1);
            A = a0 + a1; B = b0 + b1; C = c0 + c1;
        } else {
            coef(tbl + 1, A, B, C);
        }
    }
    // re-center by delta: q_guard(v) = q_src(v + delta)
    double Bg = B + 2.0 * A * delta;
    double Cg = C + B * delta + A * delta * delta;

    double As = 0.125 * A, Bs = 0.125 * Bg, Cs = 0.125 * Cg;

    // fp16 quantize A, B; fold E[v^2]=1/12 of A's rounding error into C
    __half Ah = __float2half_rn((float)As);
    __half Bh = __float2half_rn((float)Bs);
    Cs += (As - (double)__half2float(Ah)) / 12.0;

    __half2 ab = __halves2half2(Ah, Bh);                 // A low, B high
    uint2 e;
    e.x = *reinterpret_cast<unsigned*>(&ab);
    e.y = __float_as_uint((float)Cs);
    g_E[c * TBLC + tbl * SEGT + j] = e;
}

// ---- packed f32x2 helpers ----
__device__ __forceinline__ unsigned long long fma2(unsigned long long a,
                                                   unsigned long long b,
                                                   unsigned long long c)
{
    unsigned long long d;
    asm("fma.rn.f32x2 %0, %1, %2, %3;" : "=l"(d) : "l"(a), "l"(b), "l"(c));
    return d;
}
__device__ __forceinline__ unsigned long long add2(unsigned long long a,
                                                   unsigned long long b)
{
    unsigned long long d;
    asm("add.rn.f32x2 %0, %1, %2;" : "=l"(d) : "l"(a), "l"(b));
    return d;
}
__device__ __forceinline__ unsigned long long pack2(float lo, float hi)
{
    unsigned long long d;
    asm("mov.b64 %0, {%1, %2};" : "=l"(d) : "f"(lo), "f"(hi));
    return d;
}
__device__ __forceinline__ void unpack2u(unsigned long long v, unsigned& lo, unsigned& hi)
{
    asm("mov.b64 {%0, %1}, %2;" : "=r"(lo), "=r"(hi) : "l"(v));
}
// pack two f32 into one half2 register: low = lo, high = hi
__device__ __forceinline__ unsigned cvt_f16x2(float lo, float hi)
{
    unsigned d;
    asm("cvt.rn.f16x2.f32 %0, %1, %2;" : "=r"(d) : "f"(hi), "f"(lo));
    return d;
}
__device__ __forceinline__ unsigned smem_u32(const void* p)
{
    unsigned a;
    asm("{ .reg .u64 t; cvta.to.shared.u64 t, %1; cvt.u32.u64 %0, t; }"
        : "=r"(a) : "l"(p));
    return a;
}
// raw-address shared load of one 8-byte table entry
__device__ __forceinline__ void lds_entry(unsigned addr, unsigned& ab, unsigned& cc)
{
    asm("ld.shared.v2.u32 {%0, %1}, [%2];" : "=r"(ab), "=r"(cc) : "r"(addr));
}

__global__ __launch_bounds__(256, 6)
void stripe_poly_kernel(const float* __restrict__ x,
                        float* __restrict__ out,
                        PosConsts pc)
{
    __shared__ uint2 sE[TBLC];                           // 30464 B

    const int c = blockIdx.y;

    for (int k = threadIdx.x; k < TBLC; k += 256)
        sE[k] = g_E[c * TBLC + k];
    __syncthreads();

    // Pre-biased shared base: entry address = (bits(g) << 3) + sbase,
    // since bits(g) = MAGICBITS + tableIndex (table offset folded into D).
    const unsigned sbase = smem_u32(sE) - (MAGICBITS << 3);

    // thread owns ONE pixel (adjacent lanes = adjacent h -> conflict-free
    // gather footprint), processes batches in PAIRS via packed f32x2 math.
    const int pixel = blockIdx.x * 256 + threadIdx.x;    // grid.x*256 == 512*512
    const float wx = (float)(pixel >> 9);
    const float hy = (float)(pixel & 511);

    unsigned long long Pp[NTBL];
#pragma unroll
    for (int i = 0; i < NTBL; i++) {
        float P = fmaf(pc.Cx[i], wx, fmaf(pc.Cy[i], hy, pc.D[i]));
        Pp[i] = pack2(P, P);
    }

#pragma unroll 1
    for (int bp = 0; bp < BATCH / 2; bp++) {
        const int e0 = (((2 * bp)     * CHAN + c) << 18) + pixel;
        const int e1 = (((2 * bp + 1) * CHAN + c) << 18) + pixel;
        unsigned long long xp = pack2(x[e0], x[e1]);     // two batch samples
        __half2 accU2 = __float2half2_rn(0.f);
        float accC0 = 0.f, accC1 = 0.f;
#pragma unroll
        for (int i = 0; i < NTBL; i++) {
            unsigned long long ysp = fma2(HALF2K, xp, Pp[i]);  // ys (table-offset space)
            unsigned long long gp  = add2(ysp, MAGIC2);        // RNE round
            unsigned long long sfp = add2(gp, NMAGIC2);        // exact float index
            unsigned long long vp  = fma2(sfp, NEG1_2, ysp);   // v = ys - round(ys)
            unsigned g0, g1;
            unpack2u(gp, g0, g1);
            unsigned t0x, t0y, t1x, t1y;
            lds_entry(sbase + (g0 << 3), t0x, t0y);            // LEA + LDS.64
            lds_entry(sbase + (g1 << 3), t1x, t1y);
            unsigned vu0, vu1;
            unpack2u(vp, vu0, vu1);
            unsigned v2u = cvt_f16x2(__uint_as_float(vu0), __uint_as_float(vu1));
            // transpose (A0,B0),(A1,B1) -> (A0,A1),(B0,B1)
            unsigned A2u = __byte_perm(t0x, t1x, 0x5410);
            unsigned B2u = __byte_perm(t0x, t1x, 0x7632);
            __half2 v2 = *reinterpret_cast<__half2*>(&v2u);
            __half2 A2 = *reinterpret_cast<__half2*>(&A2u);
            __half2 B2 = *reinterpret_cast<__half2*>(&B2u);
            accU2 = __hfma2(v2, __hfma2(v2, A2, B2), accU2);
            accC0 += __uint_as_float(t0y);
            accC1 += __uint_as_float(t1y);
        }
        out[e0] = __low2float(accU2)  + accC0;
        out[e1] = __high2float(accU2) + accC1;
    }
}

extern "C" void kernel_launch(void* const* d_in, const int* in_sizes, int n_in,
                              void* d_out, int out_size)
{
    const float* x   = (const float*)d_in[0];   // [16, 3, 512, 512]
    const float* wts = (const float*)d_in[1];   // [8, 3, 1025]
    float* out = (float*)d_out;

    // Fold position maps analytically (host, double precision):
    //   xs = 0.5*x + (r - rmin)*S,  S = RATIO*512/dr,  r = cx*w + sgn*cy*h
    //   D absorbs: -0.5 midpoint shift AND the table base (tbl*SEGT + GUARD),
    //   so bits(round(ys)+MAGIC) = MAGICBITS + global table index.
    PosConsts pc;
    const double RATIO = (double)MAXD / (double)(MAXD + 1);
    for (int rot = 0; rot < 4; rot++) {
        double theta = (M_PI / 2.0) * ((double)rot / 4.0);
        double cx = cos(theta), cy = sin(theta);
        for (int s = 0; s < 2; s++) {
            int pos = rot * 2 + s;
            int tbl = (pos <= 1) ? 0 : pos - 1;          // pos 0,1 -> table 0
            double sgn  = (s == 0) ? 1.0 : -1.0;
            double rmin = (s == 0) ? 0.0 : -cy * (HDIM - 1);
            double rmax = (s == 0) ? (cx + cy) * (WDIM - 1) : cx * (WDIM - 1);
            double dr   = rmax - rmin;
            double S    = RATIO * (double)MAXD / dr;
            pc.Cx[tbl] = (float)(cx * S);
            pc.Cy[tbl] = (float)(sgn * cy * S);
            pc.D [tbl] = (float)(-rmin * S - 0.5 + (double)(tbl * SEGT + GUARD));
        }
    }

    prep_coef_kernel<<<(CHAN * TBLC + 255) / 256, 256>>>(wts);

    dim3 grid(WDIM * HDIM / 256, CHAN, 1);               // (1024, 3)
    stripe_poly_kernel<<<grid, 256>>>(x, out, pc);
}

// round 15
// speedup vs baseline: 1.1773x; 1.0876x over previous
#include <cuda_runtime.h>
#include <cuda_fp16.h>
#include <math.h>

#define SEGS     512
#define MAXD     512
#define NTBL     7            // pos 0+1 share a map -> pre-summed into table 0
#define GUARD    16           // guard segments each side (clamp-free eval)
#define SEGT     (SEGS + 2 * GUARD)   // 544 segments per table
#define TBLC     (NTBL * SEGT)        // 3808 entries per region
#define WDIM     512
#define HDIM     512
#define BATCH    16
#define CHAN     3
#define NW       1025

#define MAGIC     12582912.0f         // 1.5 * 2^23
#define MAGICBITS 0x4B400000u         // bit pattern of 12582912.0f

// packed f32x2 constants (lo|hi identical)
#define HALF2K    0x3F0000003F000000ULL
#define MAGIC2    0x4B4000004B400000ULL
#define NMAGIC2   0xCB400000CB400000ULL
#define NEG1_2    0xBF800000BF800000ULL

struct PosConsts {
    float Cx[NTBL];
    float Cy[NTBL];
    float D [NTBL];    // includes -0.5 midpoint shift AND the table base i*SEGT+GUARD
};

// Midpoint-centered per-segment quadratics, 1/8 folded in:
//   val(v) = C + v*(B + v*A),  v = ys - round(ys)
// 8-byte entry: .x = half2(A, B)  (A low, B high), .y = float C
// (C absorbs E[v^2]=1/12 of A's fp16 rounding error).
__device__ uint2 g_E[CHAN * TBLC];

__global__ __launch_bounds__(256)
void prep_coef_kernel(const float* __restrict__ wts)
{
    int idx = blockIdx.x * 256 + threadIdx.x;           // [0, 3*7*544)
    if (idx >= CHAN * TBLC) return;
    int j   = idx % SEGT;                               // 0..543
    int ct  = idx / SEGT;
    int c   = ct / NTBL;
    int tbl = ct - c * NTBL;

    int k  = j - GUARD;                                 // segment id (may be out of range)
    int kk = k < 0 ? 0 : (k > SEGS - 1 ? SEGS - 1 : k); // clamped source segment
    double delta = (double)(k - kk);

    double A, B, C;
    {
        auto coef = [&](int pos, double& a, double& b, double& cc) {
            const float* w = wts + (pos * CHAN + c) * NW + 2 * kk;
            double w0 = w[0], w1 = w[1], w2 = w[2];
            a  = 2.0 * (w0 + w2) - 4.0 * w1;
            b  = w2 - w0;
            cc = w1;
        };
        if (tbl == 0) {                                  // pos 0 + pos 1 summed
            double a0, b0, c0, a1, b1, c1;
            coef(0, a0, b0, c0);
            coef(1, a1, b1, c1);
            A = a0 + a1; B = b0 + b1; C = c0 + c1;
        } else {
            coef(tbl + 1, A, B, C);
        }
    }
    // re-center by delta: q_guard(v) = q_src(v + delta)
    double Bg = B + 2.0 * A * delta;
    double Cg = C + B * delta + A * delta * delta;

    double As = 0.125 * A, Bs = 0.125 * Bg, Cs = 0.125 * Cg;

    // fp16 quantize A, B; fold E[v^2]=1/12 of A's rounding error into C
    __half Ah = __float2half_rn((float)As);
    __half Bh = __float2half_rn((float)Bs);
    Cs += (As - (double)__half2float(Ah)) / 12.0;

    __half2 ab = __halves2half2(Ah, Bh);                 // A low, B high
    uint2 e;
    e.x = *reinterpret_cast<unsigned*>(&ab);
    e.y = __float_as_uint((float)Cs);
    g_E[c * TBLC + tbl * SEGT + j] = e;
}

// ---- packed f32x2 helpers ----
__device__ __forceinline__ unsigned long long fma2(unsigned long long a,
                                                   unsigned long long b,
                                                   unsigned long long c)
{
    unsigned long long d;
    asm("fma.rn.f32x2 %0, %1, %2, %3;" : "=l"(d) : "l"(a), "l"(b), "l"(c));
    return d;
}
__device__ __forceinline__ unsigned long long add2(unsigned long long a,
                                                   unsigned long long b)
{
    unsigned long long d;
    asm("add.rn.f32x2 %0, %1, %2;" : "=l"(d) : "l"(a), "l"(b));
    return d;
}
__device__ __forceinline__ unsigned long long pack2(float lo, float hi)
{
    unsigned long long d;
    asm("mov.b64 %0, {%1, %2};" : "=l"(d) : "f"(lo), "f"(hi));
    return d;
}
__device__ __forceinline__ void unpack2u(unsigned long long v, unsigned& lo, unsigned& hi)
{
    asm("mov.b64 {%0, %1}, %2;" : "=r"(lo), "=r"(hi) : "l"(v));
}
// pack two f32 into one half2 register: low = lo, high = hi
__device__ __forceinline__ unsigned cvt_f16x2(float lo, float hi)
{
    unsigned d;
    asm("cvt.rn.f16x2.f32 %0, %1, %2;" : "=r"(d) : "f"(hi), "f"(lo));
    return d;
}
__device__ __forceinline__ unsigned smem_u32(const void* p)
{
    unsigned a;
    asm("{ .reg .u64 t; cvta.to.shared.u64 t, %1; cvt.u32.u64 %0, t; }"
        : "=r"(a) : "l"(p));
    return a;
}
// raw-address shared load of one 8-byte table entry
__device__ __forceinline__ void lds_entry(unsigned addr, unsigned& ab, unsigned& cc)
{
    asm("ld.shared.v2.u32 {%0, %1}, [%2];" : "=r"(ab), "=r"(cc) : "r"(addr));
}

__global__ __launch_bounds__(512, 3)
void stripe_poly_kernel(const float* __restrict__ x,
                        float* __restrict__ out,
                        PosConsts pc)
{
    __shared__ uint2 sE[TBLC];                           // 30464 B

    const int c = blockIdx.y;

    // vectorized staging: two entries per uint4 (TBLC is even)
    {
        const uint4* gsrc = reinterpret_cast<const uint4*>(g_E + c * TBLC);
        uint4*       sdst = reinterpret_cast<uint4*>(sE);
        for (int k = threadIdx.x; k < TBLC / 2; k += 512)
            sdst[k] = gsrc[k];
    }
    __syncthreads();

    // Pre-biased shared base: entry address = (bits(g) << 3) + sbase,
    // since bits(g) = MAGICBITS + tableIndex (table offset folded into D).
    const unsigned sbase = smem_u32(sE) - (MAGICBITS << 3);

    // thread owns ONE pixel (adjacent lanes = adjacent h -> conflict-free
    // gather footprint), processes batches in PAIRS via packed f32x2 math.
    const int pixel = blockIdx.x * 512 + threadIdx.x;    // grid.x*512 == 512*512
    const float wx = (float)(pixel >> 9);
    const float hy = (float)(pixel & 511);

    unsigned long long Pp[NTBL];
#pragma unroll
    for (int i = 0; i < NTBL; i++) {
        float P = fmaf(pc.Cx[i], wx, fmaf(pc.Cy[i], hy, pc.D[i]));
        Pp[i] = pack2(P, P);
    }

#pragma unroll 1
    for (int bp = 0; bp < BATCH / 2; bp++) {
        const int e0 = (((2 * bp)     * CHAN + c) << 18) + pixel;
        const int e1 = (((2 * bp + 1) * CHAN + c) << 18) + pixel;
        unsigned long long xp = pack2(x[e0], x[e1]);     // two batch samples
        __half2 accU2 = __float2half2_rn(0.f);
        float accC0 = 0.f, accC1 = 0.f;
#pragma unroll
        for (int i = 0; i < NTBL; i++) {
            unsigned long long ysp = fma2(HALF2K, xp, Pp[i]);  // ys (table-offset space)
            unsigned long long gp  = add2(ysp, MAGIC2);        // RNE round
            unsigned long long sfp = add2(gp, NMAGIC2);        // exact float index
            unsigned long long vp  = fma2(sfp, NEG1_2, ysp);   // v = ys - round(ys)
            unsigned g0, g1;
            unpack2u(gp, g0, g1);
            unsigned t0x, t0y, t1x, t1y;
            lds_entry(sbase + (g0 << 3), t0x, t0y);            // LEA + LDS.64
            lds_entry(sbase + (g1 << 3), t1x, t1y);
            unsigned vu0, vu1;
            unpack2u(vp, vu0, vu1);
            unsigned v2u = cvt_f16x2(__uint_as_float(vu0), __uint_as_float(vu1));
            // transpose (A0,B0),(A1,B1) -> (A0,A1),(B0,B1)
            unsigned A2u = __byte_perm(t0x, t1x, 0x5410);
            unsigned B2u = __byte_perm(t0x, t1x, 0x7632);
            __half2 v2 = *reinterpret_cast<__half2*>(&v2u);
            __half2 A2 = *reinterpret_cast<__half2*>(&A2u);
            __half2 B2 = *reinterpret_cast<__half2*>(&B2u);
            accU2 = __hfma2(v2, __hfma2(v2, A2, B2), accU2);
            accC0 += __uint_as_float(t0y);
            accC1 += __uint_as_float(t1y);
        }
        out[e0] = __low2float(accU2)  + accC0;
        out[e1] = __high2float(accU2) + accC1;
    }
}

extern "C" void kernel_launch(void* const* d_in, const int* in_sizes, int n_in,
                              void* d_out, int out_size)
{
    const float* x   = (const float*)d_in[0];   // [16, 3, 512, 512]
    const float* wts = (const float*)d_in[1];   // [8, 3, 1025]
    float* out = (float*)d_out;

    // Fold position maps analytically (host, double precision):
    //   xs = 0.5*x + (r - rmin)*S,  S = RATIO*512/dr,  r = cx*w + sgn*cy*h
    //   D absorbs: -0.5 midpoint shift AND the table base (tbl*SEGT + GUARD),
    //   so bits(round(ys)+MAGIC) = MAGICBITS + global table index.
    PosConsts pc;
    const double RATIO = (double)MAXD / (double)(MAXD + 1);
    for (int rot = 0; rot < 4; rot++) {
        double theta = (M_PI / 2.0) * ((double)rot / 4.0);
        double cx = cos(theta), cy = sin(theta);
        for (int s = 0; s < 2; s++) {
            int pos = rot * 2 + s;
            int tbl = (pos <= 1) ? 0 : pos - 1;          // pos 0,1 -> table 0
            double sgn  = (s == 0) ? 1.0 : -1.0;
            double rmin = (s == 0) ? 0.0 : -cy * (HDIM - 1);
            double rmax = (s == 0) ? (cx + cy) * (WDIM - 1) : cx * (WDIM - 1);
            double dr   = rmax - rmin;
            double S    = RATIO * (double)MAXD / dr;
            pc.Cx[tbl] = (float)(cx * S);
            pc.Cy[tbl] = (float)(sgn * cy * S);
            pc.D [tbl] = (float)(-rmin * S - 0.5 + (double)(tbl * SEGT + GUARD));
        }
    }

    prep_coef_kernel<<<(CHAN * TBLC + 255) / 256, 256>>>(wts);

    dim3 grid(WDIM * HDIM / 512, CHAN, 1);               // (512, 3)
    stripe_poly_kernel<<<grid, 512>>>(x, out, pc);
}

// round 16
// speedup vs baseline: 1.2236x; 1.0393x over previous
#include <cuda_runtime.h>
#include <cuda_fp16.h>
#include <math.h>

#define SEGS     512
#define MAXD     512
#define NTBL     7            // pos 0+1 share a map -> pre-summed into table 0
#define GUARD    16           // guard segments each side (clamp-free eval)
#define SEGT     (SEGS + 2 * GUARD)   // 544 segments per table
#define TBLC     (NTBL * SEGT)        // 3808 entries per region
#define WDIM     512
#define HDIM     512
#define BATCH    16
#define CHAN     3
#define NW       1025

#define MAGIC     12582912.0f         // 1.5 * 2^23
#define MAGICBITS 0x4B400000u         // bit pattern of 12582912.0f

// packed f32x2 constants (lo|hi identical)
#define HALF2K    0x3F0000003F000000ULL
#define MAGIC2    0x4B4000004B400000ULL
#define NMAGIC2   0xCB400000CB400000ULL
#define NEG1_2    0xBF800000BF800000ULL

struct PosConsts {
    float Cx[NTBL];
    float Cy[NTBL];
    float D [NTBL];    // includes -0.5 midpoint shift AND the table base i*SEGT+GUARD
};

// Midpoint-centered per-segment quadratics, 1/8 folded in:
//   val(v) = C + v*(B + v*A),  v = ys - round(ys)
// 8-byte entry: .x = half2(A, B)  (A low, B high), .y = float C
// (C absorbs E[v^2]=1/12 of A's fp16 rounding error).
__device__ uint2 g_E[CHAN * TBLC];

__global__ __launch_bounds__(256)
void prep_coef_kernel(const float* __restrict__ wts)
{
    int idx = blockIdx.x * 256 + threadIdx.x;           // [0, 3*7*544)
    if (idx >= CHAN * TBLC) return;
    int j   = idx % SEGT;                               // 0..543
    int ct  = idx / SEGT;
    int c   = ct / NTBL;
    int tbl = ct - c * NTBL;

    int k  = j - GUARD;                                 // segment id (may be out of range)
    int kk = k < 0 ? 0 : (k > SEGS - 1 ? SEGS - 1 : k); // clamped source segment
    double delta = (double)(k - kk);

    double A, B, C;
    {
        auto coef = [&](int pos, double& a, double& b, double& cc) {
            const float* w = wts + (pos * CHAN + c) * NW + 2 * kk;
            double w0 = w[0], w1 = w[1], w2 = w[2];
            a  = 2.0 * (w0 + w2) - 4.0 * w1;
            b  = w2 - w0;
            cc = w1;
        };
        if (tbl == 0) {                                  // pos 0 + pos 1 summed
            double a0, b0, c0, a1, b1, c1;
            coef(0, a0, b0, c0);
            coef(1, a1, b1, c1);
            A = a0 + a1; B = b0 + b1; C = c0 + c1;
        } else {
            coef(tbl + 1, A, B, C);
        }
    }
    // re-center by delta: q_guard(v) = q_src(v + delta)
    double Bg = B + 2.0 * A * delta;
    double Cg = C + B * delta + A * delta * delta;

    double As = 0.125 * A, Bs = 0.125 * Bg, Cs = 0.125 * Cg;

    // fp16 quantize A, B; fold E[v^2]=1/12 of A's rounding error into C
    __half Ah = __float2half_rn((float)As);
    __half Bh = __float2half_rn((float)Bs);
    Cs += (As - (double)__half2float(Ah)) / 12.0;

    __half2 ab = __halves2half2(Ah, Bh);                 // A low, B high
    uint2 e;
    e.x = *reinterpret_cast<unsigned*>(&ab);
    e.y = __float_as_uint((float)Cs);
    g_E[c * TBLC + tbl * SEGT + j] = e;
}

// ---- packed f32x2 helpers ----
__device__ __forceinline__ unsigned long long fma2(unsigned long long a,
                                                   unsigned long long b,
                                                   unsigned long long c)
{
    unsigned long long d;
    asm("fma.rn.f32x2 %0, %1, %2, %3;" : "=l"(d) : "l"(a), "l"(b), "l"(c));
    return d;
}
__device__ __forceinline__ unsigned long long add2(unsigned long long a,
                                                   unsigned long long b)
{
    unsigned long long d;
    asm("add.rn.f32x2 %0, %1, %2;" : "=l"(d) : "l"(a), "l"(b));
    return d;
}
__device__ __forceinline__ unsigned long long pack2(float lo, float hi)
{
    unsigned long long d;
    asm("mov.b64 %0, {%1, %2};" : "=l"(d) : "f"(lo), "f"(hi));
    return d;
}
// volatile variant: kept inside loops (prevents hoisting -> register blowup)
__device__ __forceinline__ unsigned long long pack2v(float lo, float hi)
{
    unsigned long long d;
    asm volatile("mov.b64 %0, {%1, %2};" : "=l"(d) : "f"(lo), "f"(hi));
    return d;
}
__device__ __forceinline__ void unpack2u(unsigned long long v, unsigned& lo, unsigned& hi)
{
    asm("mov.b64 {%0, %1}, %2;" : "=r"(lo), "=r"(hi) : "l"(v));
}
// pack two f32 into one half2 register: low = lo, high = hi
__device__ __forceinline__ unsigned cvt_f16x2(float lo, float hi)
{
    unsigned d;
    asm("cvt.rn.f16x2.f32 %0, %1, %2;" : "=r"(d) : "f"(hi), "f"(lo));
    return d;
}
__device__ __forceinline__ unsigned smem_u32(const void* p)
{
    unsigned a;
    asm("{ .reg .u64 t; cvta.to.shared.u64 t, %1; cvt.u32.u64 %0, t; }"
        : "=r"(a) : "l"(p));
    return a;
}
// raw-address shared load of one 8-byte table entry
__device__ __forceinline__ void lds_entry(unsigned addr, unsigned& ab, unsigned& cc)
{
    asm("ld.shared.v2.u32 {%0, %1}, [%2];" : "=r"(ab), "=r"(cc) : "r"(addr));
}

__global__ __launch_bounds__(512, 4)
void stripe_poly_kernel(const float* __restrict__ x,
                        float* __restrict__ out,
                        PosConsts pc)
{
    __shared__ uint2 sE[TBLC];                           // 30464 B

    const int c = blockIdx.y;

    // vectorized staging: two entries per uint4 (TBLC is even)
    {
        const uint4* gsrc = reinterpret_cast<const uint4*>(g_E + c * TBLC);
        uint4*       sdst = reinterpret_cast<uint4*>(sE);
        for (int k = threadIdx.x; k < TBLC / 2; k += 512)
            sdst[k] = gsrc[k];
    }
    __syncthreads();

    // Pre-biased shared base: entry address = (bits(g) << 3) + sbase,
    // since bits(g) = MAGICBITS + tableIndex (table offset folded into D).
    const unsigned sbase = smem_u32(sE) - (MAGICBITS << 3);

    // thread owns ONE pixel (adjacent lanes = adjacent h -> conflict-free
    // gather footprint), processes batches in PAIRS via packed f32x2 math.
    const int pixel = blockIdx.x * 512 + threadIdx.x;    // grid.x*512 == 512*512
    const float wx = (float)(pixel >> 9);
    const float hy = (float)(pixel & 511);

    // SCALAR position terms (7 regs, not 14) — re-packed per use below
    float P[NTBL];
#pragma unroll
    for (int i = 0; i < NTBL; i++)
        P[i] = fmaf(pc.Cx[i], wx, fmaf(pc.Cy[i], hy, pc.D[i]));

#pragma unroll 1
    for (int bp = 0; bp < BATCH / 2; bp++) {
        const int e0 = (((2 * bp)     * CHAN + c) << 18) + pixel;
        const int e1 = (((2 * bp + 1) * CHAN + c) << 18) + pixel;
        unsigned long long xp = pack2(x[e0], x[e1]);     // two batch samples
        __half2 accU2 = __float2half2_rn(0.f);
        float accC0 = 0.f, accC1 = 0.f;
#pragma unroll
        for (int i = 0; i < NTBL; i++) {
            unsigned long long PP  = pack2v(P[i], P[i]); // stays in-loop (volatile)
            unsigned long long ysp = fma2(HALF2K, xp, PP);     // ys (table-offset space)
            unsigned long long gp  = add2(ysp, MAGIC2);        // RNE round
            unsigned long long sfp = add2(gp, NMAGIC2);        // exact float index
            unsigned long long vp  = fma2(sfp, NEG1_2, ysp);   // v = ys - round(ys)
            unsigned g0, g1;
            unpack2u(gp, g0, g1);
            unsigned t0x, t0y, t1x, t1y;
            lds_entry(sbase + (g0 << 3), t0x, t0y);            // LEA + LDS.64
            lds_entry(sbase + (g1 << 3), t1x, t1y);
            unsigned vu0, vu1;
            unpack2u(vp, vu0, vu1);
            unsigned v2u = cvt_f16x2(__uint_as_float(vu0), __uint_as_float(vu1));
            // transpose (A0,B0),(A1,B1) -> (A0,A1),(B0,B1)
            unsigned A2u = __byte_perm(t0x, t1x, 0x5410);
            unsigned B2u = __byte_perm(t0x, t1x, 0x7632);
            __half2 v2 = *reinterpret_cast<__half2*>(&v2u);
            __half2 A2 = *reinterpret_cast<__half2*>(&A2u);
            __half2 B2 = *reinterpret_cast<__half2*>(&B2u);
            accU2 = __hfma2(v2, __hfma2(v2, A2, B2), accU2);
            accC0 += __uint_as_float(t0y);
            accC1 += __uint_as_float(t1y);
        }
        out[e0] = __low2float(accU2)  + accC0;
        out[e1] = __high2float(accU2) + accC1;
    }
}

extern "C" void kernel_launch(void* const* d_in, const int* in_sizes, int n_in,
                              void* d_out, int out_size)
{
    const float* x   = (const float*)d_in[0];   // [16, 3, 512, 512]
    const float* wts = (const float*)d_in[1];   // [8, 3, 1025]
    float* out = (float*)d_out;

    // Fold position maps analytically (host, double precision):
    //   xs = 0.5*x + (r - rmin)*S,  S = RATIO*512/dr,  r = cx*w + sgn*cy*h
    //   D absorbs: -0.5 midpoint shift AND the table base (tbl*SEGT + GUARD),
    //   so bits(round(ys)+MAGIC) = MAGICBITS + global table index.
    PosConsts pc;
    const double RATIO = (double)MAXD / (double)(MAXD + 1);
    for (int rot = 0; rot < 4; rot++) {
        double theta = (M_PI / 2.0) * ((double)rot / 4.0);
        double cx = cos(theta), cy = sin(theta);
        for (int s = 0; s < 2; s++) {
            int pos = rot * 2 + s;
            int tbl = (pos <= 1) ? 0 : pos - 1;          // pos 0,1 -> table 0
            double sgn  = (s == 0) ? 1.0 : -1.0;
            double rmin = (s == 0) ? 0.0 : -cy * (HDIM - 1);
            double rmax = (s == 0) ? (cx + cy) * (WDIM - 1) : cx * (WDIM - 1);
            double dr   = rmax - rmin;
            double S    = RATIO * (double)MAXD / dr;
            pc.Cx[tbl] = (float)(cx * S);
            pc.Cy[tbl] = (float)(sgn * cy * S);
            pc.D [tbl] = (float)(-rmin * S - 0.5 + (double)(tbl * SEGT + GUARD));
        }
    }

    prep_coef_kernel<<<(CHAN * TBLC + 255) / 256, 256>>>(wts);

    dim3 grid(WDIM * HDIM / 512, CHAN, 1);               // (512, 3)
    stripe_poly_kernel<<<grid, 512>>>(x, out, pc);
}